// round 5
// baseline (speedup 1.0000x reference)
#include <cuda_runtime.h>

#define BB 64
#define TT 1024
#define CC 256
#define NTH 1024
#define RRq 32                 // reg rows per quarter
#define SRq 32                 // smem rows per quarter
#define TSTR 132               // fwd trsT row stride (128 used + 4)
#define ROWS_SM 192            // chase smem-resident transT rows
#define TRPAD 260              // chase trs row stride
#define NR 8                   // chase ring depth

__device__ float g_alpha[(size_t)BB * TT * CC];
__device__ float g_pmax [(size_t)BB * TT * CC];
__device__ float g_transT[CC * CC];

__device__ __forceinline__ unsigned fkey(float v) {
    unsigned u = __float_as_uint(v);
    return (u & 0x80000000u) ? ~u : (u | 0x80000000u);
}
__device__ __forceinline__ unsigned long long pack2(float a, float b) {
    unsigned long long r;
    asm("mov.b64 %0,{%1,%2};" : "=l"(r) : "f"(a), "f"(b));
    return r;
}
__device__ __forceinline__ unsigned long long addx2(unsigned long long a, unsigned long long b) {
    unsigned long long r;
    asm("add.rn.f32x2 %0,%1,%2;" : "=l"(r) : "l"(a), "l"(b));
    return r;
}
__device__ __forceinline__ void unpack2(unsigned long long p, float& a, float& b) {
    asm("mov.b64 {%0,%1},%2;" : "=f"(a), "=f"(b) : "l"(p));
}
__device__ __forceinline__ void cp16(void* smem_dst, const void* gsrc) {
    unsigned sa = (unsigned)__cvta_generic_to_shared(smem_dst);
    asm volatile("cp.async.cg.shared.global [%0],[%1],16;" :: "r"(sa), "l"(gsrc));
}

// ---------------- transpose: g_transT[c][p] = trans[p][c] -------------------
__global__ void transpose_kernel(const float* __restrict__ trans) {
    __shared__ float tile[32][33];
    int bx = blockIdx.x * 32, by = blockIdx.y * 32;
    int tx = threadIdx.x, ty = threadIdx.y;
    tile[ty][tx] = trans[(by + ty) * CC + bx + tx];
    __syncthreads();
    g_transT[(bx + ty) * CC + by + tx] = tile[tx][ty];
}

// ---------------- Forward: one CTA/batch, 1024 threads ----------------------
// Quarter h covers prev rows [h*64, h*64+63]: first 32 in regs, last 32 in smem.
__global__ __launch_bounds__(NTH, 1)
void fwd_kernel(const float* __restrict__ seq, const float* __restrict__ trans) {
    extern __shared__ float sm[];
    float* trsT  = sm;                    // [CC][TSTR], col j -> row (j/32)*64+32+(j%32)
    float* albuf = sm + CC * TSTR;        // [2][CC]
    float* part  = albuf + 2 * CC;        // [4][CC]

    const int b = blockIdx.x;
    const int tid = threadIdx.x;
    const int c = tid & (CC - 1);
    const int h = tid >> 8;               // 0..3
    const int rbase = h * 64;
    const int sbase = rbase + RRq;

    for (int idx = tid; idx < CC * 4 * SRq; idx += NTH) {
        int j = idx >> 8, cc = idx & (CC - 1);
        int row = (j >> 5) * 64 + 32 + (j & 31);
        trsT[cc * TSTR + j] = trans[row * CC + cc];
    }

    unsigned long long treg[RRq / 2];
#pragma unroll
    for (int i = 0; i < RRq / 2; i++) {
        float t0 = trans[(rbase + 2 * i) * CC + c];
        float t1 = trans[(rbase + 2 * i + 1) * CC + c];
        treg[i] = pack2(t0, t1);
    }

    const float* sb = seq + (size_t)b * TT * CC;
    float* ab = g_alpha + (size_t)b * TT * CC;
    float* pb = g_pmax + (size_t)b * TT * CC;

    if (h == 0) {
        float a0 = sb[c];
        albuf[c] = a0;
        ab[c] = a0;
    }
    __syncthreads();

    float emit_next = sb[CC + c];
    int cur = 0;
    const float* tr = trsT + c * TSTR + h * SRq;
    for (int t = 1; t < TT; t++) {
        float emit = emit_next;
        int tn = (t + 1 < TT) ? (t + 1) : (TT - 1);
        emit_next = sb[(size_t)tn * CC + c];

        const float* as = albuf + cur * CC;
        float m0 = -3.0e38f, m1 = -3.0e38f, m2 = -3.0e38f, m3 = -3.0e38f;
#pragma unroll
        for (int g = 0; g < RRq / 4; g++) {
            float4 a4 = *(const float4*)(as + rbase + 4 * g);
            float f0, f1, f2, f3;
            unpack2(addx2(pack2(a4.x, a4.y), treg[2 * g]), f0, f1);
            unpack2(addx2(pack2(a4.z, a4.w), treg[2 * g + 1]), f2, f3);
            m0 = fmaxf(m0, f0); m1 = fmaxf(m1, f1);
            m2 = fmaxf(m2, f2); m3 = fmaxf(m3, f3);
        }
#pragma unroll
        for (int g = 0; g < SRq / 4; g++) {
            float4 a4 = *(const float4*)(as + sbase + 4 * g);
            float4 t4 = *(const float4*)(tr + 4 * g);
            float f0, f1, f2, f3;
            unpack2(addx2(pack2(a4.x, a4.y), pack2(t4.x, t4.y)), f0, f1);
            unpack2(addx2(pack2(a4.z, a4.w), pack2(t4.z, t4.w)), f2, f3);
            m0 = fmaxf(m0, f0); m1 = fmaxf(m1, f1);
            m2 = fmaxf(m2, f2); m3 = fmaxf(m3, f3);
        }
        part[h * CC + c] = fmaxf(fmaxf(m0, m1), fmaxf(m2, m3));
        __syncthreads();
        float pm = fmaxf(fmaxf(part[c], part[CC + c]),
                         fmaxf(part[2 * CC + c], part[3 * CC + c]));
        if (h == 0) albuf[(cur ^ 1) * CC + c] = pm + emit;
        else if (h == 1) ab[(size_t)t * CC + c] = pm + emit;
        else if (h == 2) pb[(size_t)t * CC + c] = pm;
        cur ^= 1;
        __syncthreads();
    }
}

// ---------------- Backward chase: one warp/batch, V-match -------------------
__global__ __launch_bounds__(32, 1)
void chase_kernel(const float* __restrict__ trans, float* __restrict__ out) {
    extern __shared__ float sm[];
    float* trs   = sm;                         // [ROWS_SM][TRPAD]
    float* aring = sm + ROWS_SM * TRPAD;       // [NR][CC] alpha rows
    float* pring = aring + NR * CC;            // [NR][CC] pmax rows (row r holds pmax[r+1])

    const int b = blockIdx.x, lane = threadIdx.x;

    // Fill trs from transT (coalesced read, conflict-free write).
    for (int i = lane * 4; i < ROWS_SM * CC; i += 32 * 4) {
        int c = i >> 8, p = i & (CC - 1);
        float4 v = *(const float4*)(g_transT + c * CC + p);
        *(float4*)(trs + c * TRPAD + p) = v;
    }
    __syncwarp();

    const float* ab = g_alpha + (size_t)b * TT * CC;
    const float* pb = g_pmax + (size_t)b * TT * CC;
    float* ob = out + (size_t)b * TT * CC;

    int tag;
    {
        const float4* a4 = (const float4*)(ab + (size_t)(TT - 1) * CC);
        float4 x0 = a4[lane * 2], x1 = a4[lane * 2 + 1];
        unsigned k[8] = {fkey(x0.x), fkey(x0.y), fkey(x0.z), fkey(x0.w),
                         fkey(x1.x), fkey(x1.y), fkey(x1.z), fkey(x1.w)};
        unsigned m = k[0];
#pragma unroll
        for (int j = 1; j < 8; j++) m = (k[j] > m) ? k[j] : m;
        unsigned M = __reduce_max_sync(0xffffffffu, m);
        int pm = 0x7fffffff;
#pragma unroll
        for (int j = 7; j >= 0; j--) if (k[j] == M) pm = lane * 8 + j;
        tag = (int)__reduce_min_sync(0xffffffffu, (unsigned)pm);
    }

    auto write_row = [&](int t, int tg) {
        float4* o = (float4*)(ob + (size_t)t * CC);
        int p = lane * 8;
        float4 v0, v1;
        v0.x = (p + 0 == tg); v0.y = (p + 1 == tg);
        v0.z = (p + 2 == tg); v0.w = (p + 3 == tg);
        v1.x = (p + 4 == tg); v1.y = (p + 5 == tg);
        v1.z = (p + 6 == tg); v1.w = (p + 7 == tg);
        o[lane * 2] = v0;
        o[lane * 2 + 1] = v1;
    };
    write_row(TT - 1, tag);

    // Prime ring: groups for rows TT-2 .. TT-1-NR (alpha[r] + pmax[r+1]).
#pragma unroll
    for (int kk = 0; kk < NR; kk++) {
        int r = TT - 2 - kk;
        int sl = r & (NR - 1);
        const float* asrc = ab + (size_t)r * CC + lane * 8;
        const float* psrc = pb + (size_t)(r + 1) * CC + lane * 8;
        cp16(aring + sl * CC + lane * 8, asrc);
        cp16(aring + sl * CC + lane * 8 + 4, asrc + 4);
        cp16(pring + sl * CC + lane * 8, psrc);
        cp16(pring + sl * CC + lane * 8 + 4, psrc + 4);
        asm volatile("cp.async.commit_group;");
    }

    for (int r = TT - 2; r >= 0; r--) {
        asm volatile("cp.async.wait_group %0;" :: "n"(NR - 1));
        int sl = r & (NR - 1);
        float V = pring[sl * CC + tag];            // broadcast LDS
        const float4* rp = (const float4*)(aring + sl * CC);
        float4 xa = rp[lane * 2], xb = rp[lane * 2 + 1];

        float tc[8];
        if (tag < ROWS_SM) {
            const float4* tr4 = (const float4*)(trs + tag * TRPAD);
            float4 u0 = tr4[lane * 2], u1 = tr4[lane * 2 + 1];
            tc[0] = u0.x; tc[1] = u0.y; tc[2] = u0.z; tc[3] = u0.w;
            tc[4] = u1.x; tc[5] = u1.y; tc[6] = u1.z; tc[7] = u1.w;
        } else {
            const float4* tr4 = (const float4*)(g_transT + tag * CC);
            float4 u0 = tr4[lane * 2], u1 = tr4[lane * 2 + 1];
            tc[0] = u0.x; tc[1] = u0.y; tc[2] = u0.z; tc[3] = u0.w;
            tc[4] = u1.x; tc[5] = u1.y; tc[6] = u1.z; tc[7] = u1.w;
        }

        int bits = 0;
        bits |= (xa.x + tc[0] == V) << 0;
        bits |= (xa.y + tc[1] == V) << 1;
        bits |= (xa.z + tc[2] == V) << 2;
        bits |= (xa.w + tc[3] == V) << 3;
        bits |= (xb.x + tc[4] == V) << 4;
        bits |= (xb.y + tc[5] == V) << 5;
        bits |= (xb.z + tc[6] == V) << 6;
        bits |= (xb.w + tc[7] == V) << 7;
        unsigned mask = __ballot_sync(0xffffffffu, bits != 0);
        int leader = __ffs(mask) - 1;
        int jloc = __ffs(bits) - 1;
        int j = __shfl_sync(0xffffffffu, jloc, leader);
        tag = leader * 8 + j;
        write_row(r, tag);

        int rn = r - NR;
        if (rn >= 0) {
            int s2 = rn & (NR - 1);
            const float* asrc = ab + (size_t)rn * CC + lane * 8;
            const float* psrc = pb + (size_t)(rn + 1) * CC + lane * 8;
            cp16(aring + s2 * CC + lane * 8, asrc);
            cp16(aring + s2 * CC + lane * 8 + 4, asrc + 4);
            cp16(pring + s2 * CC + lane * 8, psrc);
            cp16(pring + s2 * CC + lane * 8 + 4, psrc + 4);
        }
        asm volatile("cp.async.commit_group;");
    }
}

extern "C" void kernel_launch(void* const* d_in, const int* in_sizes, int n_in,
                              void* d_out, int out_size) {
    const float* seq = (const float*)d_in[0];
    const float* trans = (const float*)d_in[1];
    if (n_in >= 2 && in_sizes[0] == CC * CC) {
        const float* tmp = seq; seq = trans; trans = tmp;
    }
    float* out = (float*)d_out;

    const int fwd_smem = (CC * TSTR + 6 * CC) * 4;
    const int chase_smem = (ROWS_SM * TRPAD + 2 * NR * CC) * 4;
    static int init = 0;
    if (!init) {
        cudaFuncSetAttribute(fwd_kernel, cudaFuncAttributeMaxDynamicSharedMemorySize, fwd_smem);
        cudaFuncSetAttribute(chase_kernel, cudaFuncAttributeMaxDynamicSharedMemorySize, chase_smem);
        init = 1;
    }

    transpose_kernel<<<dim3(8, 8), dim3(32, 32)>>>(trans);
    fwd_kernel<<<BB, NTH, fwd_smem>>>(seq, trans);
    chase_kernel<<<BB, 32, chase_smem>>>(trans, out);
}

// round 6
// speedup vs baseline: 1.2529x; 1.2529x over previous
#include <cuda_runtime.h>

#define BB 64
#define TT 1024
#define CC 256
#define NTH 512
#define RR 88                 // reg-resident transition rows per thread-half
#define SR 40                 // smem-resident transition rows per thread-half
#define TPAD 84               // fwd trsT row stride
#define ROWS_SM 192           // chase smem-resident transT rows
#define TRPAD 260             // chase trs row stride
#define NR 8                  // chase ring depth

__device__ float g_alpha[(size_t)BB * TT * CC];
__device__ float g_pmax [(size_t)BB * TT * CC];
__device__ float g_transT[CC * CC];

__device__ __forceinline__ unsigned fkey(float v) {
    unsigned u = __float_as_uint(v);
    return (u & 0x80000000u) ? ~u : (u | 0x80000000u);
}
__device__ __forceinline__ unsigned long long pack2(float a, float b) {
    unsigned long long r;
    asm("mov.b64 %0,{%1,%2};" : "=l"(r) : "f"(a), "f"(b));
    return r;
}
__device__ __forceinline__ unsigned long long addx2(unsigned long long a, unsigned long long b) {
    unsigned long long r;
    asm("add.rn.f32x2 %0,%1,%2;" : "=l"(r) : "l"(a), "l"(b));
    return r;
}
__device__ __forceinline__ void unpack2(unsigned long long p, float& a, float& b) {
    asm("mov.b64 {%0,%1},%2;" : "=f"(a), "=f"(b) : "l"(p));
}
__device__ __forceinline__ void cp16(void* smem_dst, const void* gsrc) {
    unsigned sa = (unsigned)__cvta_generic_to_shared(smem_dst);
    asm volatile("cp.async.cg.shared.global [%0],[%1],16;" :: "r"(sa), "l"(gsrc));
}

// ---------------- transpose: g_transT[c][p] = trans[p][c] -------------------
__global__ void transpose_kernel(const float* __restrict__ trans) {
    __shared__ float tile[32][33];
    int bx = blockIdx.x * 32, by = blockIdx.y * 32;
    int tx = threadIdx.x, ty = threadIdx.y;
    tile[ty][tx] = trans[(by + ty) * CC + bx + tx];
    __syncthreads();
    g_transT[(bx + ty) * CC + by + tx] = tile[tx][ty];
}

// ---------------- Forward: one CTA/batch, 512 threads (R2 structure) --------
__global__ __launch_bounds__(NTH, 1)
void fwd_kernel(const float* __restrict__ seq, const float* __restrict__ trans) {
    extern __shared__ float sm[];
    float* trsT  = sm;                    // [CC][TPAD]
    float* albuf = sm + CC * TPAD;        // [2][CC]
    float* part  = albuf + 2 * CC;        // [CC]

    const int b = blockIdx.x;
    const int tid = threadIdx.x;
    const int c = tid & (CC - 1);
    const int h = tid >> 8;
    const int rbase = h * 128;
    const int sbase = rbase + RR;
    const int j0 = h * SR;

    for (int idx = tid; idx < CC * 2 * SR; idx += NTH) {
        int jj = idx >> 8, cc = idx & (CC - 1);
        int row = (jj < SR) ? (RR + jj) : (128 + RR + (jj - SR));
        trsT[cc * TPAD + jj] = trans[row * CC + cc];
    }

    unsigned long long treg[RR / 2];
#pragma unroll
    for (int i = 0; i < RR / 2; i++) {
        float t0 = trans[(rbase + 2 * i) * CC + c];
        float t1 = trans[(rbase + 2 * i + 1) * CC + c];
        treg[i] = pack2(t0, t1);
    }

    const float* sb = seq + (size_t)b * TT * CC;
    float* ab = g_alpha + (size_t)b * TT * CC;
    float* pb = g_pmax + (size_t)b * TT * CC;

    if (h == 0) {
        float a0 = sb[c];
        albuf[c] = a0;
        ab[c] = a0;
    }
    __syncthreads();

    float emit_next = (h == 0) ? sb[CC + c] : 0.0f;
    int cur = 0;
    const float* tr = trsT + c * TPAD + j0;
    for (int t = 1; t < TT; t++) {
        float emit = emit_next;
        if (h == 0) {
            int tn = (t + 1 < TT) ? (t + 1) : (TT - 1);
            emit_next = sb[(size_t)tn * CC + c];
        }

        const float* as = albuf + cur * CC;
        float m0 = -3.0e38f, m1 = -3.0e38f, m2 = -3.0e38f, m3 = -3.0e38f;
#pragma unroll
        for (int g = 0; g < RR / 4; g++) {
            float4 a4 = *(const float4*)(as + rbase + 4 * g);
            float f0, f1, f2, f3;
            unpack2(addx2(pack2(a4.x, a4.y), treg[2 * g]), f0, f1);
            unpack2(addx2(pack2(a4.z, a4.w), treg[2 * g + 1]), f2, f3);
            m0 = fmaxf(m0, f0); m1 = fmaxf(m1, f1);
            m2 = fmaxf(m2, f2); m3 = fmaxf(m3, f3);
        }
#pragma unroll
        for (int g = 0; g < SR / 4; g++) {
            float4 a4 = *(const float4*)(as + sbase + 4 * g);
            float4 t4 = *(const float4*)(tr + 4 * g);
            float f0, f1, f2, f3;
            unpack2(addx2(pack2(a4.x, a4.y), pack2(t4.x, t4.y)), f0, f1);
            unpack2(addx2(pack2(a4.z, a4.w), pack2(t4.z, t4.w)), f2, f3);
            m0 = fmaxf(m0, f0); m1 = fmaxf(m1, f1);
            m2 = fmaxf(m2, f2); m3 = fmaxf(m3, f3);
        }
        float m = fmaxf(fmaxf(m0, m1), fmaxf(m2, m3));
        if (h == 1) part[c] = m;
        __syncthreads();
        if (h == 0) {
            float pm = fmaxf(m, part[c]);
            float na = pm + emit;
            albuf[(cur ^ 1) * CC + c] = na;
            ab[(size_t)t * CC + c] = na;
            pb[(size_t)t * CC + c] = pm;
        }
        cur ^= 1;
        __syncthreads();
    }
}

// ---------------- Backward chase: one warp/batch, V-match -------------------
__global__ __launch_bounds__(32, 1)
void chase_kernel(const float* __restrict__ trans, float* __restrict__ out) {
    extern __shared__ float sm[];
    float* trs   = sm;                         // [ROWS_SM][TRPAD]
    float* aring = sm + ROWS_SM * TRPAD;       // [NR][CC]
    float* pring = aring + NR * CC;            // [NR][CC] (slot r holds pmax[r+1])

    const int b = blockIdx.x, lane = threadIdx.x;

    for (int i = lane * 4; i < ROWS_SM * CC; i += 32 * 4) {
        int c = i >> 8, p = i & (CC - 1);
        float4 v = *(const float4*)(g_transT + c * CC + p);
        *(float4*)(trs + c * TRPAD + p) = v;
    }
    __syncwarp();

    const float* ab = g_alpha + (size_t)b * TT * CC;
    const float* pb = g_pmax + (size_t)b * TT * CC;
    float* ob = out + (size_t)b * TT * CC;

    int tag;
    {
        const float4* a4 = (const float4*)(ab + (size_t)(TT - 1) * CC);
        float4 x0 = a4[lane * 2], x1 = a4[lane * 2 + 1];
        unsigned k[8] = {fkey(x0.x), fkey(x0.y), fkey(x0.z), fkey(x0.w),
                         fkey(x1.x), fkey(x1.y), fkey(x1.z), fkey(x1.w)};
        unsigned m = k[0];
#pragma unroll
        for (int j = 1; j < 8; j++) m = (k[j] > m) ? k[j] : m;
        unsigned M = __reduce_max_sync(0xffffffffu, m);
        int pm = 0x7fffffff;
#pragma unroll
        for (int j = 7; j >= 0; j--) if (k[j] == M) pm = lane * 8 + j;
        tag = (int)__reduce_min_sync(0xffffffffu, (unsigned)pm);
    }

    auto write_row = [&](int t, int tg) {
        float4* o = (float4*)(ob + (size_t)t * CC);
        int p = lane * 8;
        float4 v0, v1;
        v0.x = (p + 0 == tg); v0.y = (p + 1 == tg);
        v0.z = (p + 2 == tg); v0.w = (p + 3 == tg);
        v1.x = (p + 4 == tg); v1.y = (p + 5 == tg);
        v1.z = (p + 6 == tg); v1.w = (p + 7 == tg);
        o[lane * 2] = v0;
        o[lane * 2 + 1] = v1;
    };
    write_row(TT - 1, tag);

#pragma unroll
    for (int kk = 0; kk < NR; kk++) {
        int r = TT - 2 - kk;
        int sl = r & (NR - 1);
        const float* asrc = ab + (size_t)r * CC + lane * 8;
        const float* psrc = pb + (size_t)(r + 1) * CC + lane * 8;
        cp16(aring + sl * CC + lane * 8, asrc);
        cp16(aring + sl * CC + lane * 8 + 4, asrc + 4);
        cp16(pring + sl * CC + lane * 8, psrc);
        cp16(pring + sl * CC + lane * 8 + 4, psrc + 4);
        asm volatile("cp.async.commit_group;");
    }

    for (int r = TT - 2; r >= 0; r--) {
        asm volatile("cp.async.wait_group %0;" :: "n"(NR - 1));
        int sl = r & (NR - 1);
        float V = pring[sl * CC + tag];            // broadcast LDS
        const float4* rp = (const float4*)(aring + sl * CC);
        float4 xa = rp[lane * 2], xb = rp[lane * 2 + 1];

        float tc[8];
        if (tag < ROWS_SM) {
            const float4* tr4 = (const float4*)(trs + tag * TRPAD);
            float4 u0 = tr4[lane * 2], u1 = tr4[lane * 2 + 1];
            tc[0] = u0.x; tc[1] = u0.y; tc[2] = u0.z; tc[3] = u0.w;
            tc[4] = u1.x; tc[5] = u1.y; tc[6] = u1.z; tc[7] = u1.w;
        } else {
            const float4* tr4 = (const float4*)(g_transT + tag * CC);
            float4 u0 = tr4[lane * 2], u1 = tr4[lane * 2 + 1];
            tc[0] = u0.x; tc[1] = u0.y; tc[2] = u0.z; tc[3] = u0.w;
            tc[4] = u1.x; tc[5] = u1.y; tc[6] = u1.z; tc[7] = u1.w;
        }

        int bits = 0;
        bits |= (xa.x + tc[0] == V) << 0;
        bits |= (xa.y + tc[1] == V) << 1;
        bits |= (xa.z + tc[2] == V) << 2;
        bits |= (xa.w + tc[3] == V) << 3;
        bits |= (xb.x + tc[4] == V) << 4;
        bits |= (xb.y + tc[5] == V) << 5;
        bits |= (xb.z + tc[6] == V) << 6;
        bits |= (xb.w + tc[7] == V) << 7;
        unsigned mask = __ballot_sync(0xffffffffu, bits != 0);
        int leader = __ffs(mask) - 1;
        int jloc = __ffs(bits) - 1;
        int j = __shfl_sync(0xffffffffu, jloc, leader);
        tag = leader * 8 + j;
        write_row(r, tag);

        int rn = r - NR;
        if (rn >= 0) {
            int s2 = rn & (NR - 1);
            const float* asrc = ab + (size_t)rn * CC + lane * 8;
            const float* psrc = pb + (size_t)(rn + 1) * CC + lane * 8;
            cp16(aring + s2 * CC + lane * 8, asrc);
            cp16(aring + s2 * CC + lane * 8 + 4, asrc + 4);
            cp16(pring + s2 * CC + lane * 8, psrc);
            cp16(pring + s2 * CC + lane * 8 + 4, psrc + 4);
        }
        asm volatile("cp.async.commit_group;");
    }
}

extern "C" void kernel_launch(void* const* d_in, const int* in_sizes, int n_in,
                              void* d_out, int out_size) {
    const float* seq = (const float*)d_in[0];
    const float* trans = (const float*)d_in[1];
    if (n_in >= 2 && in_sizes[0] == CC * CC) {
        const float* tmp = seq; seq = trans; trans = tmp;
    }
    float* out = (float*)d_out;

    const int fwd_smem = (CC * TPAD + 3 * CC) * 4;
    const int chase_smem = (ROWS_SM * TRPAD + 2 * NR * CC) * 4;
    static int init = 0;
    if (!init) {
        cudaFuncSetAttribute(fwd_kernel, cudaFuncAttributeMaxDynamicSharedMemorySize, fwd_smem);
        cudaFuncSetAttribute(chase_kernel, cudaFuncAttributeMaxDynamicSharedMemorySize, chase_smem);
        init = 1;
    }

    transpose_kernel<<<dim3(8, 8), dim3(32, 32)>>>(trans);
    fwd_kernel<<<BB, NTH, fwd_smem>>>(seq, trans);
    chase_kernel<<<BB, 32, chase_smem>>>(trans, out);
}